// round 13
// baseline (speedup 1.0000x reference)
#include <cuda_runtime.h>
#include <math.h>
#include <stdint.h>

#define DDIM   64
#define KCODES 2048
#define NPTS   32768
#define HW     1024
#define PTS    128            // points per CTA
#define NB     256            // 8-code blocks total
#define NBU    64             // blocks screened in pass U (512 codes)
#define TBLK   8              // blocks per smem staging tile
#define XSTR   136            // xs row stride
#define CAP    20
#define C1B    2.6e-3f        // R5/R9-proven bound constants
#define C2B    6.4e-4f
#define ABSL   0.03f

// smem layout (bytes)
#define XS_OFF   0
#define SBUF_OFF 34816                   // 2 x 20480 staging buffers
#define SXSQ_OFF (SBUF_OFF + 40960)
#define SXN_OFF  (SXSQ_OFF + 512)
#define SC_OFF   (SXN_OFF + 512)         // 128*CAP ints
#define SCNT_OFF (SC_OFF + PTS * CAP * 4)
#define SOFL_OFF (SCNT_OFF + 512)
#define SOCN_OFF (SOFL_OFF + 512)
#define SKEY_OFF (SOCN_OFF + 8)
#define SMEMSZ   (SKEY_OFF + 16)

__device__ int    g_idx[NPTS];
__device__ float  g_esq[KCODES];
__device__ float4 g_bfU[NB * 32 * 5];    // pass-U fragments (sgn = -1)
__device__ float4 g_bfL[NB * 32 * 5];    // pass-L fragments (sgn = +1)

static __device__ __forceinline__ float to_tf32(float x) {
    float r; asm("cvt.rna.tf32.f32 %0, %1;" : "=f"(r) : "f"(x)); return r;
}
static __device__ __forceinline__ unsigned long long enc_key(float dist, int code) {
    unsigned int u = __float_as_uint(dist);
    u = (u & 0x80000000u) ? ~u : (u | 0x80000000u);
    return ((unsigned long long)u << 32) | (unsigned)code;
}
static __device__ __forceinline__ uint32_t s2u(const void* p) {
    uint32_t a;
    asm("{ .reg .u64 t; cvta.to.shared.u64 t, %1; cvt.u32.u64 %0, t; }"
        : "=r"(a) : "l"(p));
    return a;
}
static __device__ __forceinline__ void cp16(uint32_t dst, const void* src) {
    asm volatile("cp.async.cg.shared.global [%0], [%1], 16;"
                 :: "r"(dst), "l"(src) : "memory");
}
#define CP_COMMIT() asm volatile("cp.async.commit_group;" ::: "memory")
#define CP_WAIT1()  asm volatile("cp.async.wait_group 1;" ::: "memory")
#define CP_WAIT0()  asm volatile("cp.async.wait_group 0;" ::: "memory")

static __device__ __forceinline__ void mma8(float& c0, float& c1, float& c2, float& c3,
                                            float a0, float a1, float a2, float a3,
                                            float b0, float b1) {
    asm("mma.sync.aligned.m16n8k8.row.col.f32.tf32.tf32.f32 "
        "{%0,%1,%2,%3}, {%4,%5,%6,%7}, {%8,%9}, {%0,%1,%2,%3};"
        : "+f"(c0), "+f"(c1), "+f"(c2), "+f"(c3)
        : "r"(__float_as_uint(a0)), "r"(__float_as_uint(a1)),
          "r"(__float_as_uint(a2)), "r"(__float_as_uint(a3)),
          "r"(__float_as_uint(b0)), "r"(__float_as_uint(b1)));
}

// ---------------------------------------------------------------------------
// Prep 1: exact esq per code (proven sequential order)
// ---------------------------------------------------------------------------
__global__ void prep_epi(const float* __restrict__ cb) {
    int k = blockIdx.x * blockDim.x + threadIdx.x;
    if (k >= KCODES) return;
    const float4* r = reinterpret_cast<const float4*>(cb + (size_t)k * DDIM);
    float4 v[16];
    #pragma unroll
    for (int i = 0; i < 16; ++i) v[i] = __ldg(&r[i]);
    float s = 0.f;
    #pragma unroll
    for (int i = 0; i < 16; ++i) {
        s = fmaf(v[i].x, v[i].x, s); s = fmaf(v[i].y, v[i].y, s);
        s = fmaf(v[i].z, v[i].z, s); s = fmaf(v[i].w, v[i].w, s);
    }
    g_esq[k] = s;
}

// ---------------------------------------------------------------------------
// Prep 2: R9-proven tf32 fragments. dims 0..63: tf32(e); 64: -h; 65: -l
// (h+l ~= esq/2); 66: sgn*(C1/2)*en; 67: sgn*((C2/2)*esq + ABSL/2); 68..: 0
// ---------------------------------------------------------------------------
__global__ void prep_bf(const float* __restrict__ cb) {
    int t = blockIdx.x * blockDim.x + threadIdx.x;    // 0..16383
    int pass = t >> 13;
    int r    = t & 8191;
    int lane = r & 31;
    int nb   = r >> 5;
    int g = lane >> 2, q = lane & 3;
    int code = nb * 8 + g;
    const float* e = cb + (size_t)code * DDIM;
    float esq = g_esq[code];
    float en  = sqrtf(esq);
    float h = to_tf32(0.5f * esq);
    float l = to_tf32(0.5f * esq - h);
    float sgn = pass ? 1.f : -1.f;
    float a66 = to_tf32(sgn * 0.5f * C1B * en);
    float a67 = to_tf32(sgn * (0.5f * C2B * esq + 0.5f * ABSL));

    float w[20];
    #pragma unroll
    for (int s = 0; s < 9; ++s) {
        int kA = s * 8 + q, kB = kA + 4;
        w[2 * s]     = (kA < 64) ? to_tf32(__ldg(&e[kA]))
                     : (kA == 64 ? -h : (kA == 65 ? -l : (kA == 66 ? a66 : a67)));
        w[2 * s + 1] = (kB < 64) ? to_tf32(__ldg(&e[kB]))
                     : (kB == 64 ? -h : (kB == 65 ? -l :
                        (kB == 66 ? a66 : (kB == 67 ? a67 : 0.f))));
    }
    w[18] = 0.f; w[19] = 0.f;
    float4* dst = (pass ? g_bfL : g_bfU) + (size_t)r * 5;
    #pragma unroll
    for (int i = 0; i < 5; ++i)
        dst[i] = make_float4(w[4 * i], w[4 * i + 1], w[4 * i + 2], w[4 * i + 3]);
}

// ---------------------------------------------------------------------------
// Main: smem-staged B; pass U (subset M) + pass L (final M, pushes) + recheck
// ---------------------------------------------------------------------------
__global__ __launch_bounds__(256, 2)
void vq_tf32(const float* __restrict__ laten, const float* __restrict__ cb,
             float* __restrict__ out) {
    extern __shared__ char smraw[];
    const uint32_t smb = s2u(smraw);
    float* xs     = reinterpret_cast<float*>(smraw + XS_OFF);
    float* sxsq   = reinterpret_cast<float*>(smraw + SXSQ_OFF);
    float* sxn    = reinterpret_cast<float*>(smraw + SXN_OFF);
    int*   sC     = reinterpret_cast<int*>(smraw + SC_OFF);
    int*   scnt   = reinterpret_cast<int*>(smraw + SCNT_OFF);
    int*   soflow = reinterpret_cast<int*>(smraw + SOFL_OFF);
    int*   socnt  = reinterpret_cast<int*>(smraw + SOCN_OFF);
    unsigned long long* skey =
        reinterpret_cast<unsigned long long*>(smraw + SKEY_OFF);

    const int tid  = threadIdx.x;
    const int lane = tid & 31;
    const int w    = tid >> 5;
    const int g = lane >> 2, q = lane & 3;
    const int r0 = w * 16 + g, r1 = r0 + 8;
    const int sblk = tid >> 5;          // staging: warp id = block-in-tile
    const uint32_t sdst = smb + SBUF_OFF + (uint32_t)((sblk << 5) + lane) * 80;

    const int p0  = blockIdx.x * PTS;
    const int b   = p0 >> 10;
    const int hw0 = p0 & 1023;
    const float* lat_b = laten + (size_t)b * (DDIM * HW) + hw0;

    // stage x tile
    #pragma unroll
    for (int i = 0; i < 8; ++i) {
        int idx = tid + i * 256;
        int d = idx >> 5, p4 = idx & 31;
        float4 v = *reinterpret_cast<const float4*>(lat_b + d * HW + p4 * 4);
        *reinterpret_cast<float4*>(&xs[d * XSTR + p4 * 4]) = v;
    }
    if (tid < PTS) scnt[tid] = 0;
    if (tid == 0) *socnt = 0;
    __syncthreads();
    if (tid < PTS) {                            // exact xsq, sequential d
        float s = 0.f;
        #pragma unroll 8
        for (int d = 0; d < DDIM; ++d) {
            float v = xs[d * XSTR + tid];
            s = fmaf(v, v, s);
        }
        sxsq[tid] = s;
        sxn[tid]  = to_tf32(sqrtf(s));
    }
    __syncthreads();

    // A fragments (R9-proven): 64,65 -> 1; 66 -> tf32(||x||); 67 -> 1; 68+ -> 0
    float a[9][4];
    #pragma unroll
    for (int s = 0; s < 9; ++s) {
        int kA = s * 8 + q, kB = kA + 4;
        float vA0, vA1, vB0, vB1;
        if (kA < 64) { vA0 = to_tf32(xs[kA * XSTR + r0]); vA1 = to_tf32(xs[kA * XSTR + r1]); }
        else if (kA == 66) { vA0 = sxn[r0]; vA1 = sxn[r1]; }
        else { vA0 = 1.f; vA1 = 1.f; }
        if (kB < 64) { vB0 = to_tf32(xs[kB * XSTR + r0]); vB1 = to_tf32(xs[kB * XSTR + r1]); }
        else if (kB == 66) { vB0 = sxn[r0]; vB1 = sxn[r1]; }
        else if (kB == 67) { vB0 = 1.f; vB1 = 1.f; }
        else { vB0 = 0.f; vB1 = 0.f; }
        a[s][0] = vA0; a[s][1] = vA1; a[s][2] = vB0; a[s][3] = vB1;
    }

    #define STAGE(SRC, nb0, half)                                              \
    do {                                                                       \
        const float4* s_ = (SRC) + ((size_t)((nb0) + sblk) * 32 + lane) * 5;   \
        uint32_t d_ = sdst + (uint32_t)(half) * 20480;                         \
        cp16(d_,      s_);     cp16(d_ + 16, s_ + 1);                          \
        cp16(d_ + 32, s_ + 2); cp16(d_ + 48, s_ + 3);                          \
        cp16(d_ + 64, s_ + 4);                                                 \
        CP_COMMIT();                                                           \
    } while (0)

    float M0 = -3.402823e+38f, M1 = -3.402823e+38f;

    // ---- Pass U: subset M over blocks 0..NBU-1 (epilogue: 4 FMNMX) ----
    STAGE(g_bfU, 0, 0);
    for (int t = 0; t < NBU / TBLK; ++t) {
        if (t + 1 < NBU / TBLK) { STAGE(g_bfU, (t + 1) * TBLK, (t + 1) & 1); CP_WAIT1(); }
        else CP_WAIT0();
        __syncthreads();
        const char* cb_ = smraw + SBUF_OFF + (t & 1) * 20480;
        #pragma unroll
        for (int blk = 0; blk < TBLK; ++blk) {
            const float4* fb = reinterpret_cast<const float4*>(
                cb_ + ((blk << 5) + lane) * 80);
            float4 f[5];                       // ARRAY: contiguous, reg-resident
            #pragma unroll
            for (int i = 0; i < 5; ++i) f[i] = fb[i];
            const float* wv = reinterpret_cast<const float*>(f);
            float c0 = 0.f, c1 = 0.f, c2 = 0.f, c3 = 0.f;
            #pragma unroll
            for (int s = 0; s < 9; ++s)
                mma8(c0, c1, c2, c3, a[s][0], a[s][1], a[s][2], a[s][3],
                     wv[2 * s], wv[2 * s + 1]);
            M0 = fmaxf(M0, fmaxf(c0, c1));
            M1 = fmaxf(M1, fmaxf(c2, c3));
        }
        __syncthreads();
    }
    // finalize M per point across the 4 q-lanes
    M0 = fmaxf(M0, __shfl_xor_sync(0xFFFFFFFFu, M0, 1));
    M0 = fmaxf(M0, __shfl_xor_sync(0xFFFFFFFFu, M0, 2));
    M1 = fmaxf(M1, __shfl_xor_sync(0xFFFFFFFFu, M1, 1));
    M1 = fmaxf(M1, __shfl_xor_sync(0xFFFFFFFFu, M1, 2));

    // ---- Pass L: all blocks, FINAL M, rare pushes (epilogue: 4 setp) ----
    STAGE(g_bfL, 0, 0);
    for (int t = 0; t < NB / TBLK; ++t) {
        if (t + 1 < NB / TBLK) { STAGE(g_bfL, (t + 1) * TBLK, (t + 1) & 1); CP_WAIT1(); }
        else CP_WAIT0();
        __syncthreads();
        const char* cb_ = smraw + SBUF_OFF + (t & 1) * 20480;
        #pragma unroll
        for (int blk = 0; blk < TBLK; ++blk) {
            const float4* fb = reinterpret_cast<const float4*>(
                cb_ + ((blk << 5) + lane) * 80);
            float4 f[5];                       // ARRAY: contiguous, reg-resident
            #pragma unroll
            for (int i = 0; i < 5; ++i) f[i] = fb[i];
            const float* wv = reinterpret_cast<const float*>(f);
            float c0 = 0.f, c1 = 0.f, c2 = 0.f, c3 = 0.f;
            #pragma unroll
            for (int s = 0; s < 9; ++s)
                mma8(c0, c1, c2, c3, a[s][0], a[s][1], a[s][2], a[s][3],
                     wv[2 * s], wv[2 * s + 1]);
            int code0 = (t * TBLK + blk) * 8 + 2 * q;
            if (c0 >= M0) { int i_ = atomicAdd(&scnt[r0], 1); if (i_ < CAP) sC[r0 * CAP + i_] = code0; }
            if (c1 >= M0) { int i_ = atomicAdd(&scnt[r0], 1); if (i_ < CAP) sC[r0 * CAP + i_] = code0 + 1; }
            if (c2 >= M1) { int i_ = atomicAdd(&scnt[r1], 1); if (i_ < CAP) sC[r1 * CAP + i_] = code0; }
            if (c3 >= M1) { int i_ = atomicAdd(&scnt[r1], 1); if (i_ < CAP) sC[r1 * CAP + i_] = code0 + 1; }
        }
        __syncthreads();
    }
    #undef STAGE

    // ---- exact recheck (proven fp32 formula) ----
    if (tid < PTS) {
        int n = scnt[tid];
        if (n >= 1 && n <= CAP) {
            float xq = sxsq[tid];
            unsigned long long best = ~0ULL;
            for (int i = 0; i < n; ++i) {
                int code = sC[tid * CAP + i];
                const float* e = cb + (size_t)code * DDIM;
                float s = 0.f;
                #pragma unroll 8
                for (int d = 0; d < DDIM; ++d)
                    s = fmaf(xs[d * XSTR + tid], __ldg(&e[d]), s);
                unsigned long long kk = enc_key(fmaf(-2.f, s, xq) + g_esq[code], code);
                if (kk < best) best = kk;
            }
            int code = (int)(best & 0xFFFFFFFFULL);
            g_idx[p0 + tid] = code;
            out[p0 + tid]   = (float)code;
        } else {
            int i = atomicAdd(socnt, 1);
            soflow[i] = tid;
        }
    }
    __syncthreads();

    // ---- cooperative exact fallback (overflow; rare) ----
    const int nf = *socnt;
    for (int i = 0; i < nf; ++i) {
        int pl = soflow[i];
        if (tid == 0) *skey = ~0ULL;
        __syncthreads();
        float xq = sxsq[pl];
        unsigned long long mk = ~0ULL;
        for (int c = tid * 8; c < tid * 8 + 8; ++c) {
            const float* e = cb + (size_t)c * DDIM;
            float s = 0.f;
            #pragma unroll 8
            for (int d = 0; d < DDIM; ++d)
                s = fmaf(xs[d * XSTR + pl], __ldg(&e[d]), s);
            unsigned long long kk = enc_key(fmaf(-2.f, s, xq) + g_esq[c], c);
            if (kk < mk) mk = kk;
        }
        atomicMin(skey, mk);
        __syncthreads();
        if (tid == 0) {
            int code = (int)(*skey & 0xFFFFFFFFULL);
            g_idx[p0 + pl] = code;
            out[p0 + pl]   = (float)code;
        }
        __syncthreads();
    }
}

// ---------------------------------------------------------------------------
// Gather: coalesced stores, cached cb reads
// ---------------------------------------------------------------------------
__global__ __launch_bounds__(256)
void gather_kernel(const float* __restrict__ cb, float* __restrict__ out) {
    __shared__ int sidx[64];
    const int tid = threadIdx.x;
    const int b   = blockIdx.x >> 4;
    const int hw0 = (blockIdx.x & 15) * 64;
    if (tid < 64) sidx[tid] = g_idx[b * HW + hw0 + tid];
    __syncthreads();
    const int hw4   = tid & 15;
    const int dbase = tid >> 4;
    const int k0 = sidx[hw4 * 4], k1 = sidx[hw4 * 4 + 1];
    const int k2 = sidx[hw4 * 4 + 2], k3 = sidx[hw4 * 4 + 3];
    #pragma unroll
    for (int it = 0; it < 4; ++it) {
        int d = dbase + it * 16;
        float4 v;
        v.x = __ldg(&cb[k0 * DDIM + d]);
        v.y = __ldg(&cb[k1 * DDIM + d]);
        v.z = __ldg(&cb[k2 * DDIM + d]);
        v.w = __ldg(&cb[k3 * DDIM + d]);
        *reinterpret_cast<float4*>(
            &out[NPTS + (size_t)b * (DDIM * HW) + d * HW + hw0 + hw4 * 4]) = v;
    }
}

extern "C" void kernel_launch(void* const* d_in, const int* in_sizes, int n_in,
                              void* d_out, int out_size) {
    const float* laten = (const float*)d_in[0];   // (32, 64, 32, 32) f32
    const float* cb    = (const float*)d_in[1];   // (2048, 64) f32
    float* out = (float*)d_out;                   // [32768 idx | 2097152 quant]

    cudaFuncSetAttribute(vq_tf32, cudaFuncAttributeMaxDynamicSharedMemorySize, SMEMSZ);

    prep_epi<<<KCODES / 256, 256>>>(cb);
    prep_bf<<<(2 * NB * 32) / 256, 256>>>(cb);
    vq_tf32<<<NPTS / PTS, 256, SMEMSZ>>>(laten, cb, out);
    gather_kernel<<<(32 * HW) / 64, 256>>>(cb, out);
}

// round 15
// speedup vs baseline: 1.7671x; 1.7671x over previous
#include <cuda_runtime.h>
#include <cuda_fp16.h>
#include <math.h>
#include <stdint.h>

#define DDIM   64
#define KCODES 2048
#define NPTS   32768
#define HW     1024
#define PTS    128            // points per CTA
#define NB     256            // 8-code blocks total
#define NBU    64             // blocks screened in pass U (512 codes)
#define XSTR   136            // xs row stride
#define CAP    24
#define C1B    2.6e-3f        // R5/R9/R13-proven bound constants
#define C2B    6.4e-4f
#define ABSL   0.03f

// smem layout (bytes)
#define XS_OFF   0
#define SXSQ_OFF 34816
#define SXN_OFF  (SXSQ_OFF + 512)
#define SC_OFF   (SXN_OFF + 512)          // 128*CAP ints
#define SCNT_OFF (SC_OFF + PTS * CAP * 4)
#define SOFL_OFF (SCNT_OFF + 512)
#define SOCN_OFF (SOFL_OFF + 512)
#define SKEY_OFF (SOCN_OFF + 8)
#define SMEMSZ   (SKEY_OFF + 16)

__device__ int   g_idx[NPTS];
__device__ float g_esq[KCODES];
__device__ uint4 g_bfU[NB * 32 * 3];     // fp16 fragments, pass U (sgn=-1)
__device__ uint4 g_bfL[NB * 32 * 3];     // fp16 fragments, pass L (sgn=+1)

static __device__ __forceinline__ unsigned long long enc_key(float dist, int code) {
    unsigned int u = __float_as_uint(dist);
    u = (u & 0x80000000u) ? ~u : (u | 0x80000000u);
    return ((unsigned long long)u << 32) | (unsigned)code;
}
static __device__ __forceinline__ uint32_t pack_h2(float lo, float hi) {
    return (uint32_t)__half_as_ushort(__float2half_rn(lo))
         | ((uint32_t)__half_as_ushort(__float2half_rn(hi)) << 16);
}
static __device__ __forceinline__ void mma16816(float& c0, float& c1, float& c2, float& c3,
                                                uint32_t a0, uint32_t a1, uint32_t a2,
                                                uint32_t a3, uint32_t b0, uint32_t b1) {
    asm("mma.sync.aligned.m16n8k16.row.col.f32.f16.f16.f32 "
        "{%0,%1,%2,%3}, {%4,%5,%6,%7}, {%8,%9}, {%0,%1,%2,%3};"
        : "+f"(c0), "+f"(c1), "+f"(c2), "+f"(c3)
        : "r"(a0), "r"(a1), "r"(a2), "r"(a3), "r"(b0), "r"(b1));
}

// ---------------------------------------------------------------------------
// Prep 1: exact esq per code (proven sequential order)
// ---------------------------------------------------------------------------
__global__ void prep_epi(const float* __restrict__ cb) {
    int k = blockIdx.x * blockDim.x + threadIdx.x;
    if (k >= KCODES) return;
    const float4* r = reinterpret_cast<const float4*>(cb + (size_t)k * DDIM);
    float4 v[16];
    #pragma unroll
    for (int i = 0; i < 16; ++i) v[i] = __ldg(&r[i]);
    float s = 0.f;
    #pragma unroll
    for (int i = 0; i < 16; ++i) {
        s = fmaf(v[i].x, v[i].x, s); s = fmaf(v[i].y, v[i].y, s);
        s = fmaf(v[i].z, v[i].z, s); s = fmaf(v[i].w, v[i].w, s);
    }
    g_esq[k] = s;
}

// ---------------------------------------------------------------------------
// Prep 2: fp16 m16n8k16 B fragments, K=80.
// dims 0..63: e; 64: -h; 65: -l (h+l ~= esq/2 in fp16); 66: sgn*(C1/2)*en;
// 67: sgn*((C2/2)*esq + ABSL/2); 68..79: 0.
// Per (pass, nb, lane): 5 steps x (b0,b1) = 10 u32 + 2 pad = 3 uint4.
// ---------------------------------------------------------------------------
__global__ void prep_bf(const float* __restrict__ cb) {
    int t = blockIdx.x * blockDim.x + threadIdx.x;    // 0..16383
    if (t >= 2 * NB * 32) return;
    int pass = t >> 13;
    int r    = t & 8191;
    int lane = r & 31;
    int nb   = r >> 5;
    int g = lane >> 2, q = lane & 3;
    int code = nb * 8 + g;
    const float* e = cb + (size_t)code * DDIM;
    float esq = g_esq[code];
    float en  = sqrtf(esq);
    float h = __half2float(__float2half_rn(0.5f * esq));
    float l = 0.5f * esq - h;
    float sgn = pass ? 1.f : -1.f;
    float c1n = sgn * 0.5f * C1B * en;
    float c2a = sgn * (0.5f * C2B * esq + 0.5f * ABSL);

    uint32_t wd[12];
    #pragma unroll
    for (int s = 0; s < 5; ++s) {
        int k0 = s * 16 + 2 * q;
        float v0, v1, v2, v3;
        #define VB(K, OUT) do { int k_ = (K); \
            OUT = (k_ < 64) ? __ldg(&e[k_]) \
                : (k_ == 64 ? -h : (k_ == 65 ? -l \
                : (k_ == 66 ? c1n : (k_ == 67 ? c2a : 0.f)))); } while (0)
        VB(k0, v0); VB(k0 + 1, v1); VB(k0 + 8, v2); VB(k0 + 9, v3);
        #undef VB
        wd[2 * s]     = pack_h2(v0, v1);
        wd[2 * s + 1] = pack_h2(v2, v3);
    }
    wd[10] = 0u; wd[11] = 0u;
    uint4* dst = (pass ? g_bfL : g_bfU) + (size_t)r * 3;
    dst[0] = make_uint4(wd[0], wd[1], wd[2], wd[3]);
    dst[1] = make_uint4(wd[4], wd[5], wd[6], wd[7]);
    dst[2] = make_uint4(wd[8], wd[9], wd[10], wd[11]);
}

// ---------------------------------------------------------------------------
// Main: fp16 mma; pass U (subset M over 512 codes) + pass L (final M, pushes)
// + exact recheck. 256 thr = 8 warps x m16 rows. Direct-__ldg double buffer.
// ---------------------------------------------------------------------------
__global__ __launch_bounds__(256, 2)
void vq_h16(const float* __restrict__ laten, const float* __restrict__ cb,
            float* __restrict__ out) {
    extern __shared__ char smraw[];
    float* xs     = reinterpret_cast<float*>(smraw + XS_OFF);
    float* sxsq   = reinterpret_cast<float*>(smraw + SXSQ_OFF);
    float* sxn    = reinterpret_cast<float*>(smraw + SXN_OFF);
    int*   sC     = reinterpret_cast<int*>(smraw + SC_OFF);
    int*   scnt   = reinterpret_cast<int*>(smraw + SCNT_OFF);
    int*   soflow = reinterpret_cast<int*>(smraw + SOFL_OFF);
    int*   socnt  = reinterpret_cast<int*>(smraw + SOCN_OFF);
    unsigned long long* skey =
        reinterpret_cast<unsigned long long*>(smraw + SKEY_OFF);

    const int tid  = threadIdx.x;
    const int lane = tid & 31;
    const int w    = tid >> 5;
    const int g = lane >> 2, q = lane & 3;
    const int r0 = w * 16 + g, r1 = r0 + 8;

    const int p0  = blockIdx.x * PTS;
    const int b   = p0 >> 10;
    const int hw0 = p0 & 1023;
    const float* lat_b = laten + (size_t)b * (DDIM * HW) + hw0;

    // stage x tile
    #pragma unroll
    for (int i = 0; i < 8; ++i) {
        int idx = tid + i * 256;
        int d = idx >> 5, p4 = idx & 31;
        float4 v = *reinterpret_cast<const float4*>(lat_b + d * HW + p4 * 4);
        *reinterpret_cast<float4*>(&xs[d * XSTR + p4 * 4]) = v;
    }
    if (tid < PTS) scnt[tid] = 0;
    if (tid == 0) *socnt = 0;
    __syncthreads();
    if (tid < PTS) {                            // exact xsq, sequential d
        float s = 0.f;
        #pragma unroll 8
        for (int d = 0; d < DDIM; ++d) {
            float v = xs[d * XSTR + tid];
            s = fmaf(v, v, s);
        }
        sxsq[tid] = s;
        sxn[tid]  = sqrtf(s);
    }
    __syncthreads();

    // A fragments (fp16): dims 0..63 = x; 64,65,67 -> 1; 66 -> ||x||; 68+ -> 0
    uint32_t a[5][4];
    #pragma unroll
    for (int s = 0; s < 5; ++s) {
        int k0 = s * 16 + 2 * q;
        float v00, v01, v10, v11, v20, v21, v30, v31;
        #define VA(K, ROW, OUT) do { int k_ = (K); \
            OUT = (k_ < 64) ? xs[k_ * XSTR + (ROW)] \
                : (k_ == 66 ? sxn[(ROW)] \
                : ((k_ == 64 || k_ == 65 || k_ == 67) ? 1.f : 0.f)); } while (0)
        VA(k0,     r0, v00); VA(k0 + 1, r0, v01);
        VA(k0,     r1, v10); VA(k0 + 1, r1, v11);
        VA(k0 + 8, r0, v20); VA(k0 + 9, r0, v21);
        VA(k0 + 8, r1, v30); VA(k0 + 9, r1, v31);
        #undef VA
        a[s][0] = pack_h2(v00, v01);
        a[s][1] = pack_h2(v10, v11);
        a[s][2] = pack_h2(v20, v21);
        a[s][3] = pack_h2(v30, v31);
    }

    float M0 = -3.402823e+38f, M1 = -3.402823e+38f;
    const uint4* baseU = g_bfU + (size_t)lane * 3;
    const uint4* baseL = g_bfL + (size_t)lane * 3;
    uint4 bufA[3], bufB[3];

    // ---- Pass U: subset M over blocks 0..NBU-1 (epilogue: 4 FMNMX) ----
    #pragma unroll
    for (int i = 0; i < 3; ++i) bufA[i] = __ldg(baseU + i);
    for (int nb = 0; nb < NBU; nb += 2) {
        #pragma unroll
        for (int i = 0; i < 3; ++i) bufB[i] = __ldg(baseU + (size_t)(nb + 1) * 96 + i);
        {
            const uint32_t* wv = reinterpret_cast<const uint32_t*>(bufA);
            float c0 = 0.f, c1 = 0.f, c2 = 0.f, c3 = 0.f;
            #pragma unroll
            for (int s = 0; s < 5; ++s)
                mma16816(c0, c1, c2, c3, a[s][0], a[s][1], a[s][2], a[s][3],
                         wv[2 * s], wv[2 * s + 1]);
            M0 = fmaxf(M0, fmaxf(c0, c1));
            M1 = fmaxf(M1, fmaxf(c2, c3));
        }
        if (nb + 2 < NBU) {
            #pragma unroll
            for (int i = 0; i < 3; ++i) bufA[i] = __ldg(baseU + (size_t)(nb + 2) * 96 + i);
        }
        {
            const uint32_t* wv = reinterpret_cast<const uint32_t*>(bufB);
            float c0 = 0.f, c1 = 0.f, c2 = 0.f, c3 = 0.f;
            #pragma unroll
            for (int s = 0; s < 5; ++s)
                mma16816(c0, c1, c2, c3, a[s][0], a[s][1], a[s][2], a[s][3],
                         wv[2 * s], wv[2 * s + 1]);
            M0 = fmaxf(M0, fmaxf(c0, c1));
            M1 = fmaxf(M1, fmaxf(c2, c3));
        }
    }
    // finalize M per point across the 4 q-lanes
    M0 = fmaxf(M0, __shfl_xor_sync(0xFFFFFFFFu, M0, 1));
    M0 = fmaxf(M0, __shfl_xor_sync(0xFFFFFFFFu, M0, 2));
    M1 = fmaxf(M1, __shfl_xor_sync(0xFFFFFFFFu, M1, 1));
    M1 = fmaxf(M1, __shfl_xor_sync(0xFFFFFFFFu, M1, 2));

    // ---- Pass L: all blocks, FINAL M, rare pushes (epilogue: 4 setp) ----
    #pragma unroll
    for (int i = 0; i < 3; ++i) bufA[i] = __ldg(baseL + i);
    for (int nb = 0; nb < NB; nb += 2) {
        #pragma unroll
        for (int i = 0; i < 3; ++i) bufB[i] = __ldg(baseL + (size_t)(nb + 1) * 96 + i);
        {
            const uint32_t* wv = reinterpret_cast<const uint32_t*>(bufA);
            float c0 = 0.f, c1 = 0.f, c2 = 0.f, c3 = 0.f;
            #pragma unroll
            for (int s = 0; s < 5; ++s)
                mma16816(c0, c1, c2, c3, a[s][0], a[s][1], a[s][2], a[s][3],
                         wv[2 * s], wv[2 * s + 1]);
            int code0 = nb * 8 + 2 * q;
            if (c0 >= M0) { int i_ = atomicAdd(&scnt[r0], 1); if (i_ < CAP) sC[r0 * CAP + i_] = code0; }
            if (c1 >= M0) { int i_ = atomicAdd(&scnt[r0], 1); if (i_ < CAP) sC[r0 * CAP + i_] = code0 + 1; }
            if (c2 >= M1) { int i_ = atomicAdd(&scnt[r1], 1); if (i_ < CAP) sC[r1 * CAP + i_] = code0; }
            if (c3 >= M1) { int i_ = atomicAdd(&scnt[r1], 1); if (i_ < CAP) sC[r1 * CAP + i_] = code0 + 1; }
        }
        if (nb + 2 < NB) {
            #pragma unroll
            for (int i = 0; i < 3; ++i) bufA[i] = __ldg(baseL + (size_t)(nb + 2) * 96 + i);
        }
        {
            const uint32_t* wv = reinterpret_cast<const uint32_t*>(bufB);
            float c0 = 0.f, c1 = 0.f, c2 = 0.f, c3 = 0.f;
            #pragma unroll
            for (int s = 0; s < 5; ++s)
                mma16816(c0, c1, c2, c3, a[s][0], a[s][1], a[s][2], a[s][3],
                         wv[2 * s], wv[2 * s + 1]);
            int code0 = (nb + 1) * 8 + 2 * q;
            if (c0 >= M0) { int i_ = atomicAdd(&scnt[r0], 1); if (i_ < CAP) sC[r0 * CAP + i_] = code0; }
            if (c1 >= M0) { int i_ = atomicAdd(&scnt[r0], 1); if (i_ < CAP) sC[r0 * CAP + i_] = code0 + 1; }
            if (c2 >= M1) { int i_ = atomicAdd(&scnt[r1], 1); if (i_ < CAP) sC[r1 * CAP + i_] = code0; }
            if (c3 >= M1) { int i_ = atomicAdd(&scnt[r1], 1); if (i_ < CAP) sC[r1 * CAP + i_] = code0 + 1; }
        }
    }
    __syncthreads();

    // ---- exact recheck (proven fp32 formula) ----
    if (tid < PTS) {
        int n = scnt[tid];
        if (n >= 1 && n <= CAP) {
            float xq = sxsq[tid];
            unsigned long long best = ~0ULL;
            for (int i = 0; i < n; ++i) {
                int code = sC[tid * CAP + i];
                const float* e = cb + (size_t)code * DDIM;
                float s = 0.f;
                #pragma unroll 8
                for (int d = 0; d < DDIM; ++d)
                    s = fmaf(xs[d * XSTR + tid], __ldg(&e[d]), s);
                unsigned long long kk = enc_key(fmaf(-2.f, s, xq) + g_esq[code], code);
                if (kk < best) best = kk;
            }
            int code = (int)(best & 0xFFFFFFFFULL);
            g_idx[p0 + tid] = code;
            out[p0 + tid]   = (float)code;
        } else {
            int i = atomicAdd(socnt, 1);
            soflow[i] = tid;
        }
    }
    __syncthreads();

    // ---- cooperative exact fallback (overflow / empty; rare) ----
    const int nf = *socnt;
    for (int i = 0; i < nf; ++i) {
        int pl = soflow[i];
        if (tid == 0) *skey = ~0ULL;
        __syncthreads();
        float xq = sxsq[pl];
        unsigned long long mk = ~0ULL;
        for (int c = tid * 8; c < tid * 8 + 8; ++c) {
            const float* e = cb + (size_t)c * DDIM;
            float s = 0.f;
            #pragma unroll 8
            for (int d = 0; d < DDIM; ++d)
                s = fmaf(xs[d * XSTR + pl], __ldg(&e[d]), s);
            unsigned long long kk = enc_key(fmaf(-2.f, s, xq) + g_esq[c], c);
            if (kk < mk) mk = kk;
        }
        atomicMin(skey, mk);
        __syncthreads();
        if (tid == 0) {
            int code = (int)(*skey & 0xFFFFFFFFULL);
            g_idx[p0 + pl] = code;
            out[p0 + pl]   = (float)code;
        }
        __syncthreads();
    }
}

// ---------------------------------------------------------------------------
// Gather: coalesced stores, cached cb reads
// ---------------------------------------------------------------------------
__global__ __launch_bounds__(256)
void gather_kernel(const float* __restrict__ cb, float* __restrict__ out) {
    __shared__ int sidx[64];
    const int tid = threadIdx.x;
    const int b   = blockIdx.x >> 4;
    const int hw0 = (blockIdx.x & 15) * 64;
    if (tid < 64) sidx[tid] = g_idx[b * HW + hw0 + tid];
    __syncthreads();
    const int hw4   = tid & 15;
    const int dbase = tid >> 4;
    const int k0 = sidx[hw4 * 4], k1 = sidx[hw4 * 4 + 1];
    const int k2 = sidx[hw4 * 4 + 2], k3 = sidx[hw4 * 4 + 3];
    #pragma unroll
    for (int it = 0; it < 4; ++it) {
        int d = dbase + it * 16;
        float4 v;
        v.x = __ldg(&cb[k0 * DDIM + d]);
        v.y = __ldg(&cb[k1 * DDIM + d]);
        v.z = __ldg(&cb[k2 * DDIM + d]);
        v.w = __ldg(&cb[k3 * DDIM + d]);
        *reinterpret_cast<float4*>(
            &out[NPTS + (size_t)b * (DDIM * HW) + d * HW + hw0 + hw4 * 4]) = v;
    }
}

extern "C" void kernel_launch(void* const* d_in, const int* in_sizes, int n_in,
                              void* d_out, int out_size) {
    const float* laten = (const float*)d_in[0];   // (32, 64, 32, 32) f32
    const float* cb    = (const float*)d_in[1];   // (2048, 64) f32
    float* out = (float*)d_out;                   // [32768 idx | 2097152 quant]

    cudaFuncSetAttribute(vq_h16, cudaFuncAttributeMaxDynamicSharedMemorySize, SMEMSZ);

    prep_epi<<<KCODES / 256, 256>>>(cb);
    prep_bf<<<(2 * NB * 32) / 256, 256>>>(cb);
    vq_h16<<<NPTS / PTS, 256, SMEMSZ>>>(laten, cb, out);
    gather_kernel<<<(32 * HW) / 64, 256>>>(cb, out);
}